// round 13
// baseline (speedup 1.0000x reference)
#include <cuda_runtime.h>
#include <cuda_fp16.h>
#include <cstdint>

// Problem constants
#define BB   2
#define SS   4096
#define DD   1024
#define HH   16
#define HD   64
#define NB   32           // S / STEP
#define STEP 128
#define MM   (BB*SS)      // 8192 rows

// ---------------------------------------------------------------------------
// Scratch (static device globals; no allocation)
// ---------------------------------------------------------------------------
__device__ __half g_Qh[MM*DD];
__device__ __half g_Kh[MM*DD];
__device__ __half g_Vh[MM*DD];
__device__ __half g_AOh[MM*DD];
__device__ float  g_P [MM*DD];

__device__ __half g_hidh[MM*DD];
// Transposed weights [n,k], fp16
__device__ __half g_wqt[DD*DD];
__device__ __half g_wkt[DD*DD];
__device__ __half g_wvt[DD*DD];
__device__ __half g_wot[DD*DD];

// ---------------------------------------------------------------------------
// Helpers
// ---------------------------------------------------------------------------
__device__ __forceinline__ uint32_t smem_to_u32(const void* smem_ptr) {
    uint32_t addr;
    asm("{ .reg .u64 tmp; cvta.to.shared.u64 tmp, %1; cvt.u32.u64 %0, tmp; }"
        : "=r"(addr) : "l"(smem_ptr));
    return addr;
}

__device__ __forceinline__ void cp16(uint32_t dst, const void* src) {
    asm volatile("cp.async.cg.shared.global [%0], [%1], 16;\n" :: "r"(dst), "l"(src) : "memory");
}

__device__ __forceinline__ void ldsm_x4(uint32_t* r, uint32_t addr) {
    asm volatile("ldmatrix.sync.aligned.m8n8.x4.shared.b16 {%0,%1,%2,%3}, [%4];"
        : "=r"(r[0]), "=r"(r[1]), "=r"(r[2]), "=r"(r[3]) : "r"(addr));
}

__device__ __forceinline__ void ldsm_x4_t(uint32_t* r, uint32_t addr) {
    asm volatile("ldmatrix.sync.aligned.m8n8.x4.trans.shared.b16 {%0,%1,%2,%3}, [%4];"
        : "=r"(r[0]), "=r"(r[1]), "=r"(r[2]), "=r"(r[3]) : "r"(addr));
}

// D += A*B  (m16n8k16, fp16 in, fp32 accum)
__device__ __forceinline__ void mma16816h(float* d, const uint32_t* a, const uint32_t* b) {
    asm volatile(
        "mma.sync.aligned.m16n8k16.row.col.f32.f16.f16.f32 "
        "{%0,%1,%2,%3}, {%4,%5,%6,%7}, {%8,%9}, {%0,%1,%2,%3};"
        : "+f"(d[0]), "+f"(d[1]), "+f"(d[2]), "+f"(d[3])
        : "r"(a[0]), "r"(a[1]), "r"(a[2]), "r"(a[3]), "r"(b[0]), "r"(b[1]));
}

__device__ __forceinline__ uint32_t h2u(float a, float b) {
    __half2 h = __floats2half2_rn(a, b);
    return *(uint32_t*)&h;
}

// ---------------------------------------------------------------------------
// Conversion kernels: fp32 -> fp16
// ---------------------------------------------------------------------------
__global__ void __launch_bounds__(256)
cvt_h(const float* __restrict__ x, __half* __restrict__ y)
{
    int i = (blockIdx.x * 256 + threadIdx.x) * 8;
    float4 v0 = *(const float4*)(x + i);
    float4 v1 = *(const float4*)(x + i + 4);
    __half2* yp = (__half2*)(y + i);
    yp[0] = __floats2half2_rn(v0.x, v0.y);
    yp[1] = __floats2half2_rn(v0.z, v0.w);
    yp[2] = __floats2half2_rn(v1.x, v1.y);
    yp[3] = __floats2half2_rn(v1.z, v1.w);
}

// All 4 weights [K,N] -> [n,k] fp16 (transposed), one launch, grid.z selects.
__global__ void __launch_bounds__(256)
cvt_h_T4(const float* __restrict__ W0, const float* __restrict__ W1,
         const float* __restrict__ W2, const float* __restrict__ W3,
         __half* __restrict__ T0, __half* __restrict__ T1,
         __half* __restrict__ T2, __half* __restrict__ T3)
{
    const int z = blockIdx.z;
    const float* W = (z == 0) ? W0 : (z == 1) ? W1 : (z == 2) ? W2 : W3;
    __half*      T = (z == 0) ? T0 : (z == 1) ? T1 : (z == 2) ? T2 : T3;

    __shared__ float t[32][33];
    int tx = threadIdx.x & 31, ty = threadIdx.x >> 5;  // ty 0..7
    int n0 = blockIdx.x * 32, k0 = blockIdx.y * 32;
    #pragma unroll
    for (int r = ty; r < 32; r += 8)
        t[r][tx] = W[(size_t)(k0 + r) * DD + n0 + tx];
    __syncthreads();
    #pragma unroll
    for (int r = ty; r < 32; r += 8)
        T[(size_t)(n0 + r) * DD + k0 + tx] = __float2half_rn(t[tx][r]);
}

// ---------------------------------------------------------------------------
// HMMA GEMM core: 128x256 CTA tile, warp tile 64x64 (2x4 warps), BK=64,
// 3-stage cp.async pipeline, 1 CTA/SM, full register budget.
// Pitch 144 B -> conflict-free cp.async stores + ldmatrix reads.
// smem traffic: 86 B/cyc of 128 B/cyc crossbar (was 156 -> oversubscribed).
// ---------------------------------------------------------------------------
#define NCH 16                      // 1024 / 64
#define GP  144                     // smem row pitch (9 x 16B)
#define GB_OFF (128 * GP)           // B tile offset inside stage
#define GSTAGE (384 * GP)           // 55296 B
#define GEMM_SMEM (3 * GSTAGE)      // 165888 B -> 1 CTA/SM

__device__ __forceinline__ void load_stage(
    uint32_t sbase,
    const __half* __restrict__ A, const __half* __restrict__ B,
    int block_row, int block_col, int k0, int tid)
{
    // A: 128 rows x 8 chunks = 1024 cp16
    #pragma unroll
    for (int t = 0; t < 4; t++) {
        int idx = tid + t * 256;
        int r = idx >> 3, c = idx & 7;
        cp16(sbase + (uint32_t)(r * GP + c * 16),
             A + (size_t)(block_row + r) * DD + k0 + c * 8);
    }
    // B: 256 rows x 8 chunks = 2048 cp16
    #pragma unroll
    for (int t = 0; t < 8; t++) {
        int idx = tid + t * 256;
        int r = idx >> 3, c = idx & 7;
        cp16(sbase + GB_OFF + (uint32_t)(r * GP + c * 16),
             B + (size_t)(block_col + r) * DD + k0 + c * 8);
    }
    asm volatile("cp.async.commit_group;\n" ::: "memory");
}

// Mainloop computing acc[4][8][4] for a 128x256 tile.
__device__ __forceinline__ void gemm_main(
    float acc[4][8][4], uint32_t smem_base,
    const __half* __restrict__ A, const __half* __restrict__ B,
    int block_row, int block_col, int tid)
{
    const int wid  = tid >> 5;
    const int lane = tid & 31;
    const int wm = wid & 1;     // 2 M-slabs of 64
    const int wn = wid >> 1;    // 4 N-slabs of 64

    load_stage(smem_base + 0 * GSTAGE, A, B, block_row, block_col, 0,  tid);
    load_stage(smem_base + 1 * GSTAGE, A, B, block_row, block_col, 64, tid);

    const uint32_t a_row = (uint32_t)(wm * 64 + (lane & 15));
    const uint32_t a_sel = (uint32_t)(lane >> 4);
    const uint32_t b_row = (uint32_t)(wn * 64 + (lane & 7) + ((lane >> 4) << 3));
    const uint32_t b_sel = (uint32_t)((lane >> 3) & 1);

    int st = 0;                // stage of chunk cc (mod 3)
    for (int cc = 0; cc < NCH; cc++) {
        if (cc + 1 < NCH) asm volatile("cp.async.wait_group 1;\n" ::: "memory");
        else              asm volatile("cp.async.wait_group 0;\n" ::: "memory");
        __syncthreads();

        if (cc + 2 < NCH) {
            int pst = st + 2; if (pst >= 3) pst -= 3;
            load_stage(smem_base + pst * GSTAGE,
                       A, B, block_row, block_col, (cc + 2) * 64, tid);
        }

        const uint32_t sb = smem_base + st * GSTAGE;

        #pragma unroll
        for (int ks = 0; ks < 4; ks++) {
            const uint32_t ach = (2 * ks + a_sel) * 16;
            const uint32_t bch = (2 * ks + b_sel) * 16;

            uint32_t af[4][4];
            #pragma unroll
            for (int mt = 0; mt < 4; mt++)
                ldsm_x4(af[mt], sb + (a_row + mt * 16) * GP + ach);
            uint32_t bf[4][4];
            #pragma unroll
            for (int g = 0; g < 4; g++)
                ldsm_x4(bf[g], sb + GB_OFF + (b_row + g * 16) * GP + bch);

            #pragma unroll
            for (int mt = 0; mt < 4; mt++)
                #pragma unroll
                for (int nt = 0; nt < 8; nt++)
                    mma16816h(acc[mt][nt], af[mt], &bf[nt >> 1][(nt & 1) * 2]);
        }
        if (++st == 3) st = 0;
    }
}

// Fused QKV GEMM: fp16 output. grid.z selects weight/bias/output.
__global__ void __launch_bounds__(256, 1)
gemm_qkv(const __half* __restrict__ A,
         const __half* __restrict__ Bq, const __half* __restrict__ Bk,
         const __half* __restrict__ Bv,
         const float* __restrict__ bq, const float* __restrict__ bk,
         const float* __restrict__ bv,
         __half* __restrict__ Cq, __half* __restrict__ Ck, __half* __restrict__ Cv)
{
    extern __shared__ __align__(128) char smem[];
    const int z = blockIdx.z;
    const __half* B = (z == 0) ? Bq : (z == 1) ? Bk : Bv;
    const float* bias = (z == 0) ? bq : (z == 1) ? bk : bv;
    __half* C = (z == 0) ? Cq : (z == 1) ? Ck : Cv;

    const int tid = threadIdx.x;
    const int block_col = blockIdx.x * 256;
    const int block_row = blockIdx.y * 128;

    float acc[4][8][4];
    #pragma unroll
    for (int i = 0; i < 4; i++)
        #pragma unroll
        for (int j = 0; j < 8; j++)
            #pragma unroll
            for (int e = 0; e < 4; e++) acc[i][j][e] = 0.f;

    gemm_main(acc, smem_to_u32(smem), A, B, block_row, block_col, tid);

    const int wid = tid >> 5, lane = tid & 31;
    const int row0 = block_row + (wid & 1) * 64 + (lane >> 2);
    const int col0 = block_col + (wid >> 1) * 64 + (lane & 3) * 2;
    #pragma unroll
    for (int mt = 0; mt < 4; mt++) {
        int r = row0 + mt * 16;
        #pragma unroll
        for (int nt = 0; nt < 8; nt++) {
            int ccol = col0 + nt * 8;
            float2 bv2 = *(const float2*)(bias + ccol);
            __half2 v0 = __floats2half2_rn(acc[mt][nt][0] + bv2.x, acc[mt][nt][1] + bv2.y);
            __half2 v1 = __floats2half2_rn(acc[mt][nt][2] + bv2.x, acc[mt][nt][3] + bv2.y);
            *(__half2*)(C + (size_t)r * DD + ccol)       = v0;
            *(__half2*)(C + (size_t)(r + 8) * DD + ccol) = v1;
        }
    }
}

// O-projection GEMM: fp32 output.
__global__ void __launch_bounds__(256, 1)
gemm_h(const __half* __restrict__ A, const __half* __restrict__ B,
       const float* __restrict__ bias, float* __restrict__ C)
{
    extern __shared__ __align__(128) char smem[];
    const int tid = threadIdx.x;
    const int block_col = blockIdx.x * 256;
    const int block_row = blockIdx.y * 128;

    float acc[4][8][4];
    #pragma unroll
    for (int i = 0; i < 4; i++)
        #pragma unroll
        for (int j = 0; j < 8; j++)
            #pragma unroll
            for (int e = 0; e < 4; e++) acc[i][j][e] = 0.f;

    gemm_main(acc, smem_to_u32(smem), A, B, block_row, block_col, tid);

    const int wid = tid >> 5, lane = tid & 31;
    const int row0 = block_row + (wid & 1) * 64 + (lane >> 2);
    const int col0 = block_col + (wid >> 1) * 64 + (lane & 3) * 2;
    #pragma unroll
    for (int mt = 0; mt < 4; mt++) {
        int r = row0 + mt * 16;
        #pragma unroll
        for (int nt = 0; nt < 8; nt++) {
            int ccol = col0 + nt * 8;
            float2 bv = *(const float2*)(bias + ccol);
            float2 v0 = { acc[mt][nt][0] + bv.x, acc[mt][nt][1] + bv.y };
            float2 v1 = { acc[mt][nt][2] + bv.x, acc[mt][nt][3] + bv.y };
            *(float2*)(C + (size_t)r * DD + ccol)       = v0;
            *(float2*)(C + (size_t)(r + 8) * DD + ccol) = v1;
        }
    }
}

// ---------------------------------------------------------------------------
// Tensor-core attention. One CTA per (b, h, n): 128 queries x kcnt keys.
// 8 warps x 16 query rows. K processed in chunks of 64 keys. 2 CTAs/SM.
// ---------------------------------------------------------------------------
#define AP 144                                   // smem row pitch (bytes)
#define ATTN_Q_OFF 0
#define ATTN_K_OFF (128 * AP)
#define ATTN_V_OFF (ATTN_K_OFF + 256 * AP)
#define ATTN_SMEM  (ATTN_V_OFF + 256 * AP)       // 92160 B

__global__ void __launch_bounds__(256, 2)
attn_tc(const __half* __restrict__ Q, const __half* __restrict__ K,
        const __half* __restrict__ V, __half* __restrict__ AO)
{
    extern __shared__ __align__(128) char sm[];
    const uint32_t sb = smem_to_u32(sm);

    const int h = blockIdx.x;
    const int n = blockIdx.y;
    const int b = blockIdx.z;
    const int tid = threadIdx.x;
    const int w = tid >> 5;
    const int lane = tid & 31;

    const size_t rowbase = (size_t)b * SS + (size_t)n * STEP;
    const int kcnt = (n == NB - 1) ? 128 : 256;

    const __half* Qg = Q + rowbase * DD + h * HD;
    const __half* Kg = K + rowbase * DD + h * HD;
    const __half* Vg = V + rowbase * DD + h * HD;
    for (int idx = tid; idx < 128 * 8; idx += 256) {
        int r = idx >> 3, c = idx & 7;
        *(uint4*)(sm + ATTN_Q_OFF + r * AP + c * 16) =
            *(const uint4*)(Qg + (size_t)r * DD + c * 8);
    }
    for (int idx = tid; idx < kcnt * 8; idx += 256) {
        int r = idx >> 3, c = idx & 7;
        *(uint4*)(sm + ATTN_K_OFF + r * AP + c * 16) =
            *(const uint4*)(Kg + (size_t)r * DD + c * 8);
        *(uint4*)(sm + ATTN_V_OFF + r * AP + c * 16) =
            *(const uint4*)(Vg + (size_t)r * DD + c * 8);
    }
    __syncthreads();

    uint32_t qf[4][4];
    {
        const uint32_t a_row = (uint32_t)(w * 16 + (lane & 15));
        const uint32_t a_sel = (uint32_t)(lane >> 4);
        #pragma unroll
        for (int t = 0; t < 4; t++)
            ldsm_x4(qf[t], sb + ATTN_Q_OFF + a_row * AP + (2 * t + a_sel) * 16);
    }

    float oacc[8][4];
    #pragma unroll
    for (int j = 0; j < 8; j++)
        #pragma unroll
        for (int e = 0; e < 4; e++) oacc[j][e] = 0.f;
    float rs_lo = 0.f, rs_hi = 0.f;

    const uint32_t b_row = (uint32_t)((lane & 7) + ((lane >> 4) << 3));
    const uint32_t b_sel = (uint32_t)((lane >> 3) & 1);
    const uint32_t v_row = (uint32_t)((lane & 7) + (((lane >> 3) & 1) << 3));
    const uint32_t v_col = (uint32_t)(((lane >> 4) & 1) << 4);

    const int nch = kcnt >> 6;
    for (int ch = 0; ch < nch; ch++) {
        const int kb = ch * 64;

        float sacc[8][4];
        #pragma unroll
        for (int j = 0; j < 8; j++)
            #pragma unroll
            for (int e = 0; e < 4; e++) sacc[j][e] = 0.f;

        #pragma unroll
        for (int g = 0; g < 4; g++) {
            #pragma unroll
            for (int t = 0; t < 4; t++) {
                uint32_t kf[4];
                ldsm_x4(kf, sb + ATTN_K_OFF + (kb + g * 16 + b_row) * AP
                              + (2 * t + b_sel) * 16);
                mma16816h(sacc[2 * g],     qf[t], &kf[0]);
                mma16816h(sacc[2 * g + 1], qf[t], &kf[2]);
            }
        }

        uint32_t pa[4][4];
        #pragma unroll
        for (int j = 0; j < 8; j++) {
            float p0 = __expf(sacc[j][0] * 0.125f);
            float p1 = __expf(sacc[j][1] * 0.125f);
            float p2 = __expf(sacc[j][2] * 0.125f);
            float p3 = __expf(sacc[j][3] * 0.125f);
            rs_lo += p0 + p1;
            rs_hi += p2 + p3;
            pa[j >> 1][(j & 1) * 2 + 0] = h2u(p0, p1);
            pa[j >> 1][(j & 1) * 2 + 1] = h2u(p2, p3);
        }

        #pragma unroll
        for (int t = 0; t < 4; t++) {
            #pragma unroll
            for (int dp = 0; dp < 4; dp++) {
                uint32_t vf[4];
                ldsm_x4_t(vf, sb + ATTN_V_OFF + (kb + t * 16 + v_row) * AP
                                + dp * 32 + v_col);
                mma16816h(oacc[2 * dp],     pa[t], &vf[0]);
                mma16816h(oacc[2 * dp + 1], pa[t], &vf[2]);
            }
        }
    }

    rs_lo += __shfl_xor_sync(0xffffffffu, rs_lo, 1);
    rs_lo += __shfl_xor_sync(0xffffffffu, rs_lo, 2);
    rs_hi += __shfl_xor_sync(0xffffffffu, rs_hi, 1);
    rs_hi += __shfl_xor_sync(0xffffffffu, rs_hi, 2);
    const float il = 1.f / rs_lo;
    const float ih = 1.f / rs_hi;

    const size_t row = rowbase + w * 16 + (lane >> 2);
    const int col0 = h * HD + (lane & 3) * 2;
    #pragma unroll
    for (int j = 0; j < 8; j++) {
        int c = col0 + j * 8;
        *(__half2*)(AO + row * DD + c) =
            __floats2half2_rn(oacc[j][0] * il, oacc[j][1] * il);
        *(__half2*)(AO + (row + 8) * DD + c) =
            __floats2half2_rn(oacc[j][2] * ih, oacc[j][3] * ih);
    }
}

// ---------------------------------------------------------------------------
// Residual add + LayerNorm
// ---------------------------------------------------------------------------
__global__ void __launch_bounds__(256)
ln_kernel(const float* __restrict__ hid, const float* __restrict__ proj,
          const float* __restrict__ w, const float* __restrict__ bb,
          float* __restrict__ out)
{
    const int row = blockIdx.x;
    const int tid = threadIdx.x;

    float4 hv = *(const float4*)(hid  + (size_t)row * DD + tid * 4);
    float4 pv = *(const float4*)(proj + (size_t)row * DD + tid * 4);
    float x0 = hv.x + pv.x, x1 = hv.y + pv.y, x2 = hv.z + pv.z, x3 = hv.w + pv.w;

    __shared__ float red1[8];
    __shared__ float red2[8];

    float s = x0 + x1 + x2 + x3;
    #pragma unroll
    for (int off = 16; off > 0; off >>= 1) s += __shfl_xor_sync(0xffffffffu, s, off);
    if ((tid & 31) == 0) red1[tid >> 5] = s;
    __syncthreads();
    float tot = red1[0] + red1[1] + red1[2] + red1[3]
              + red1[4] + red1[5] + red1[6] + red1[7];
    float mean = tot * (1.f / DD);

    float d0 = x0 - mean, d1 = x1 - mean, d2 = x2 - mean, d3 = x3 - mean;
    float s2 = d0*d0 + d1*d1 + d2*d2 + d3*d3;
    #pragma unroll
    for (int off = 16; off > 0; off >>= 1) s2 += __shfl_xor_sync(0xffffffffu, s2, off);
    if ((tid & 31) == 0) red2[tid >> 5] = s2;
    __syncthreads();
    float tot2 = red2[0] + red2[1] + red2[2] + red2[3]
               + red2[4] + red2[5] + red2[6] + red2[7];
    float rstd = rsqrtf(tot2 * (1.f / DD) + 1e-5f);

    float4 wv = *(const float4*)(w  + tid * 4);
    float4 bv = *(const float4*)(bb + tid * 4);
    float4 ov;
    ov.x = d0 * rstd * wv.x + bv.x;
    ov.y = d1 * rstd * wv.y + bv.y;
    ov.z = d2 * rstd * wv.z + bv.z;
    ov.w = d3 * rstd * wv.w + bv.w;
    *(float4*)(out + (size_t)row * DD + tid * 4) = ov;
}

// ---------------------------------------------------------------------------
extern "C" void kernel_launch(void* const* d_in, const int* in_sizes, int n_in,
                              void* d_out, int out_size)
{
    const float* hid = (const float*)d_in[0];
    const float* Wq  = (const float*)d_in[1];
    const float* bq  = (const float*)d_in[2];
    const float* Wk  = (const float*)d_in[3];
    const float* bk  = (const float*)d_in[4];
    const float* Wv  = (const float*)d_in[5];
    const float* bv  = (const float*)d_in[6];
    const float* Wo  = (const float*)d_in[7];
    const float* bo  = (const float*)d_in[8];
    const float* lnw = (const float*)d_in[9];
    const float* lnb = (const float*)d_in[10];
    float* out = (float*)d_out;

    __half *Qh, *Kh, *Vh, *AOh;
    float *Pb;
    cudaGetSymbolAddress((void**)&Qh,  g_Qh);
    cudaGetSymbolAddress((void**)&Kh,  g_Kh);
    cudaGetSymbolAddress((void**)&Vh,  g_Vh);
    cudaGetSymbolAddress((void**)&AOh, g_AOh);
    cudaGetSymbolAddress((void**)&Pb,  g_P);

    __half *hidh, *wqt, *wkt, *wvt, *wot;
    cudaGetSymbolAddress((void**)&hidh, g_hidh);
    cudaGetSymbolAddress((void**)&wqt,  g_wqt);
    cudaGetSymbolAddress((void**)&wkt,  g_wkt);
    cudaGetSymbolAddress((void**)&wvt,  g_wvt);
    cudaGetSymbolAddress((void**)&wot,  g_wot);

    static bool attr_set = false;
    if (!attr_set) {
        cudaFuncSetAttribute(attn_tc,
                             cudaFuncAttributeMaxDynamicSharedMemorySize, ATTN_SMEM);
        cudaFuncSetAttribute(gemm_qkv,
                             cudaFuncAttributeMaxDynamicSharedMemorySize, GEMM_SMEM);
        cudaFuncSetAttribute(gemm_h,
                             cudaFuncAttributeMaxDynamicSharedMemorySize, GEMM_SMEM);
        attr_set = true;
    }

    // fp16 conversions: hidden states + all 4 weights (single fused launch)
    cvt_h<<<MM * DD / (256 * 8), 256>>>(hid, hidh);
    dim3 tg(32, 32, 4);
    cvt_h_T4<<<tg, 256>>>(Wq, Wk, Wv, Wo, wqt, wkt, wvt, wot);

    // Fused Q/K/V projections (fp16 HMMA, fp16 out), 128x256 tiles
    dim3 gq(DD / 256, MM / 128, 3);  // (4, 64, 3)
    gemm_qkv<<<gq, 256, GEMM_SMEM>>>(hidh, wqt, wkt, wvt, bq, bk, bv, Qh, Kh, Vh);

    // Tensor-core attention (fp16 in/out), 2 CTAs/SM
    dim3 ag(HH, NB, BB);             // (16, 32, 2)
    attn_tc<<<ag, 256, ATTN_SMEM>>>(Qh, Kh, Vh, AOh);

    // O projection (fp32 out)
    dim3 gg(DD / 256, MM / 128);     // (4, 64)
    gemm_h<<<gg, 256, GEMM_SMEM>>>(AOh, wot, bo, Pb);

    // Residual + LayerNorm
    ln_kernel<<<MM, 256>>>(hid, Pb, lnw, lnb, out);
}

// round 14
// speedup vs baseline: 1.0065x; 1.0065x over previous
#include <cuda_runtime.h>
#include <cuda_fp16.h>
#include <cstdint>

// Problem constants
#define BB   2
#define SS   4096
#define DD   1024
#define HH   16
#define HD   64
#define NB   32           // S / STEP
#define STEP 128
#define MM   (BB*SS)      // 8192 rows

// ---------------------------------------------------------------------------
// Scratch (static device globals; no allocation)
// ---------------------------------------------------------------------------
__device__ __half g_Qh[MM*DD];
__device__ __half g_Kh[MM*DD];
__device__ __half g_Vh[MM*DD];
__device__ __half g_AOh[MM*DD];
__device__ float  g_P [MM*DD];

__device__ __half g_hidh[MM*DD];
// Transposed weights [n,k], fp16
__device__ __half g_wqt[DD*DD];
__device__ __half g_wkt[DD*DD];
__device__ __half g_wvt[DD*DD];
__device__ __half g_wot[DD*DD];

// ---------------------------------------------------------------------------
// Helpers
// ---------------------------------------------------------------------------
__device__ __forceinline__ uint32_t smem_to_u32(const void* smem_ptr) {
    uint32_t addr;
    asm("{ .reg .u64 tmp; cvta.to.shared.u64 tmp, %1; cvt.u32.u64 %0, tmp; }"
        : "=r"(addr) : "l"(smem_ptr));
    return addr;
}

__device__ __forceinline__ void cp16(uint32_t dst, const void* src) {
    asm volatile("cp.async.cg.shared.global [%0], [%1], 16;\n" :: "r"(dst), "l"(src) : "memory");
}

__device__ __forceinline__ void ldsm_x4(uint32_t* r, uint32_t addr) {
    asm volatile("ldmatrix.sync.aligned.m8n8.x4.shared.b16 {%0,%1,%2,%3}, [%4];"
        : "=r"(r[0]), "=r"(r[1]), "=r"(r[2]), "=r"(r[3]) : "r"(addr));
}

__device__ __forceinline__ void ldsm_x4_t(uint32_t* r, uint32_t addr) {
    asm volatile("ldmatrix.sync.aligned.m8n8.x4.trans.shared.b16 {%0,%1,%2,%3}, [%4];"
        : "=r"(r[0]), "=r"(r[1]), "=r"(r[2]), "=r"(r[3]) : "r"(addr));
}

// D += A*B  (m16n8k16, fp16 in, fp32 accum)
__device__ __forceinline__ void mma16816h(float* d, const uint32_t* a, const uint32_t* b) {
    asm volatile(
        "mma.sync.aligned.m16n8k16.row.col.f32.f16.f16.f32 "
        "{%0,%1,%2,%3}, {%4,%5,%6,%7}, {%8,%9}, {%0,%1,%2,%3};"
        : "+f"(d[0]), "+f"(d[1]), "+f"(d[2]), "+f"(d[3])
        : "r"(a[0]), "r"(a[1]), "r"(a[2]), "r"(a[3]), "r"(b[0]), "r"(b[1]));
}

__device__ __forceinline__ uint32_t h2u(float a, float b) {
    __half2 h = __floats2half2_rn(a, b);
    return *(uint32_t*)&h;
}

// ---------------------------------------------------------------------------
// Conversion kernels: fp32 -> fp16
// ---------------------------------------------------------------------------
__global__ void __launch_bounds__(256)
cvt_h(const float* __restrict__ x, __half* __restrict__ y)
{
    int i = (blockIdx.x * 256 + threadIdx.x) * 8;
    float4 v0 = *(const float4*)(x + i);
    float4 v1 = *(const float4*)(x + i + 4);
    __half2* yp = (__half2*)(y + i);
    yp[0] = __floats2half2_rn(v0.x, v0.y);
    yp[1] = __floats2half2_rn(v0.z, v0.w);
    yp[2] = __floats2half2_rn(v1.x, v1.y);
    yp[3] = __floats2half2_rn(v1.z, v1.w);
}

// All 4 weights [K,N] -> [n,k] fp16 (transposed), one launch, grid.z selects.
__global__ void __launch_bounds__(256)
cvt_h_T4(const float* __restrict__ W0, const float* __restrict__ W1,
         const float* __restrict__ W2, const float* __restrict__ W3,
         __half* __restrict__ T0, __half* __restrict__ T1,
         __half* __restrict__ T2, __half* __restrict__ T3)
{
    const int z = blockIdx.z;
    const float* W = (z == 0) ? W0 : (z == 1) ? W1 : (z == 2) ? W2 : W3;
    __half*      T = (z == 0) ? T0 : (z == 1) ? T1 : (z == 2) ? T2 : T3;

    __shared__ float t[32][33];
    int tx = threadIdx.x & 31, ty = threadIdx.x >> 5;  // ty 0..7
    int n0 = blockIdx.x * 32, k0 = blockIdx.y * 32;
    #pragma unroll
    for (int r = ty; r < 32; r += 8)
        t[r][tx] = W[(size_t)(k0 + r) * DD + n0 + tx];
    __syncthreads();
    #pragma unroll
    for (int r = ty; r < 32; r += 8)
        T[(size_t)(n0 + r) * DD + k0 + tx] = __float2half_rn(t[tx][r]);
}

// ---------------------------------------------------------------------------
// HMMA GEMM core: 128x256 CTA tile, warp tile 64x64 (2x4 warps), BK=64,
// 3-stage cp.async pipeline, 1 CTA/SM, full register budget.
// Pitch 144 B -> conflict-free cp.async stores + ldmatrix reads.
// smem traffic: 86 B/cyc of 128 B/cyc crossbar (was 156 -> oversubscribed).
// ---------------------------------------------------------------------------
#define NCH 16                      // 1024 / 64
#define GP  144                     // smem row pitch (9 x 16B)
#define GB_OFF (128 * GP)           // B tile offset inside stage
#define GSTAGE (384 * GP)           // 55296 B
#define GEMM_SMEM (3 * GSTAGE)      // 165888 B -> 1 CTA/SM

__device__ __forceinline__ void load_stage(
    uint32_t sbase,
    const __half* __restrict__ A, const __half* __restrict__ B,
    int block_row, int block_col, int k0, int tid)
{
    // A: 128 rows x 8 chunks = 1024 cp16
    #pragma unroll
    for (int t = 0; t < 4; t++) {
        int idx = tid + t * 256;
        int r = idx >> 3, c = idx & 7;
        cp16(sbase + (uint32_t)(r * GP + c * 16),
             A + (size_t)(block_row + r) * DD + k0 + c * 8);
    }
    // B: 256 rows x 8 chunks = 2048 cp16
    #pragma unroll
    for (int t = 0; t < 8; t++) {
        int idx = tid + t * 256;
        int r = idx >> 3, c = idx & 7;
        cp16(sbase + GB_OFF + (uint32_t)(r * GP + c * 16),
             B + (size_t)(block_col + r) * DD + k0 + c * 8);
    }
    asm volatile("cp.async.commit_group;\n" ::: "memory");
}

// Mainloop computing acc[4][8][4] for a 128x256 tile.
__device__ __forceinline__ void gemm_main(
    float acc[4][8][4], uint32_t smem_base,
    const __half* __restrict__ A, const __half* __restrict__ B,
    int block_row, int block_col, int tid)
{
    const int wid  = tid >> 5;
    const int lane = tid & 31;
    const int wm = wid & 1;     // 2 M-slabs of 64
    const int wn = wid >> 1;    // 4 N-slabs of 64

    load_stage(smem_base + 0 * GSTAGE, A, B, block_row, block_col, 0,  tid);
    load_stage(smem_base + 1 * GSTAGE, A, B, block_row, block_col, 64, tid);

    const uint32_t a_row = (uint32_t)(wm * 64 + (lane & 15));
    const uint32_t a_sel = (uint32_t)(lane >> 4);
    const uint32_t b_row = (uint32_t)(wn * 64 + (lane & 7) + ((lane >> 4) << 3));
    const uint32_t b_sel = (uint32_t)((lane >> 3) & 1);

    int st = 0;                // stage of chunk cc (mod 3)
    for (int cc = 0; cc < NCH; cc++) {
        if (cc + 1 < NCH) asm volatile("cp.async.wait_group 1;\n" ::: "memory");
        else              asm volatile("cp.async.wait_group 0;\n" ::: "memory");
        __syncthreads();

        if (cc + 2 < NCH) {
            int pst = st + 2; if (pst >= 3) pst -= 3;
            load_stage(smem_base + pst * GSTAGE,
                       A, B, block_row, block_col, (cc + 2) * 64, tid);
        }

        const uint32_t sb = smem_base + st * GSTAGE;

        #pragma unroll
        for (int ks = 0; ks < 4; ks++) {
            const uint32_t ach = (2 * ks + a_sel) * 16;
            const uint32_t bch = (2 * ks + b_sel) * 16;

            uint32_t af[4][4];
            #pragma unroll
            for (int mt = 0; mt < 4; mt++)
                ldsm_x4(af[mt], sb + (a_row + mt * 16) * GP + ach);
            uint32_t bf[4][4];
            #pragma unroll
            for (int g = 0; g < 4; g++)
                ldsm_x4(bf[g], sb + GB_OFF + (b_row + g * 16) * GP + bch);

            #pragma unroll
            for (int mt = 0; mt < 4; mt++)
                #pragma unroll
                for (int nt = 0; nt < 8; nt++)
                    mma16816h(acc[mt][nt], af[mt], &bf[nt >> 1][(nt & 1) * 2]);
        }
        if (++st == 3) st = 0;
    }
}

// Fused QKV GEMM: fp16 output. grid.z selects weight/bias/output.
__global__ void __launch_bounds__(256, 1)
gemm_qkv(const __half* __restrict__ A,
         const __half* __restrict__ Bq, const __half* __restrict__ Bk,
         const __half* __restrict__ Bv,
         const float* __restrict__ bq, const float* __restrict__ bk,
         const float* __restrict__ bv,
         __half* __restrict__ Cq, __half* __restrict__ Ck, __half* __restrict__ Cv)
{
    extern __shared__ __align__(128) char smem[];
    const int z = blockIdx.z;
    const __half* B = (z == 0) ? Bq : (z == 1) ? Bk : Bv;
    const float* bias = (z == 0) ? bq : (z == 1) ? bk : bv;
    __half* C = (z == 0) ? Cq : (z == 1) ? Ck : Cv;

    const int tid = threadIdx.x;
    const int block_col = blockIdx.x * 256;
    const int block_row = blockIdx.y * 128;

    float acc[4][8][4];
    #pragma unroll
    for (int i = 0; i < 4; i++)
        #pragma unroll
        for (int j = 0; j < 8; j++)
            #pragma unroll
            for (int e = 0; e < 4; e++) acc[i][j][e] = 0.f;

    gemm_main(acc, smem_to_u32(smem), A, B, block_row, block_col, tid);

    const int wid = tid >> 5, lane = tid & 31;
    const int row0 = block_row + (wid & 1) * 64 + (lane >> 2);
    const int col0 = block_col + (wid >> 1) * 64 + (lane & 3) * 2;
    #pragma unroll
    for (int mt = 0; mt < 4; mt++) {
        int r = row0 + mt * 16;
        #pragma unroll
        for (int nt = 0; nt < 8; nt++) {
            int ccol = col0 + nt * 8;
            float2 bv2 = *(const float2*)(bias + ccol);
            __half2 v0 = __floats2half2_rn(acc[mt][nt][0] + bv2.x, acc[mt][nt][1] + bv2.y);
            __half2 v1 = __floats2half2_rn(acc[mt][nt][2] + bv2.x, acc[mt][nt][3] + bv2.y);
            *(__half2*)(C + (size_t)r * DD + ccol)       = v0;
            *(__half2*)(C + (size_t)(r + 8) * DD + ccol) = v1;
        }
    }
}

// O-projection GEMM: fp32 output.
__global__ void __launch_bounds__(256, 1)
gemm_h(const __half* __restrict__ A, const __half* __restrict__ B,
       const float* __restrict__ bias, float* __restrict__ C)
{
    extern __shared__ __align__(128) char smem[];
    const int tid = threadIdx.x;
    const int block_col = blockIdx.x * 256;
    const int block_row = blockIdx.y * 128;

    float acc[4][8][4];
    #pragma unroll
    for (int i = 0; i < 4; i++)
        #pragma unroll
        for (int j = 0; j < 8; j++)
            #pragma unroll
            for (int e = 0; e < 4; e++) acc[i][j][e] = 0.f;

    gemm_main(acc, smem_to_u32(smem), A, B, block_row, block_col, tid);

    const int wid = tid >> 5, lane = tid & 31;
    const int row0 = block_row + (wid & 1) * 64 + (lane >> 2);
    const int col0 = block_col + (wid >> 1) * 64 + (lane & 3) * 2;
    #pragma unroll
    for (int mt = 0; mt < 4; mt++) {
        int r = row0 + mt * 16;
        #pragma unroll
        for (int nt = 0; nt < 8; nt++) {
            int ccol = col0 + nt * 8;
            float2 bv = *(const float2*)(bias + ccol);
            float2 v0 = { acc[mt][nt][0] + bv.x, acc[mt][nt][1] + bv.y };
            float2 v1 = { acc[mt][nt][2] + bv.x, acc[mt][nt][3] + bv.y };
            *(float2*)(C + (size_t)r * DD + ccol)       = v0;
            *(float2*)(C + (size_t)(r + 8) * DD + ccol) = v1;
        }
    }
}

// ---------------------------------------------------------------------------
// Tensor-core attention. One CTA per (b, h, n): 128 queries x kcnt keys.
// 8 warps x 16 query rows. K processed in chunks of 64 keys. 2 CTAs/SM.
// ---------------------------------------------------------------------------
#define AP 144                                   // smem row pitch (bytes)
#define ATTN_Q_OFF 0
#define ATTN_K_OFF (128 * AP)
#define ATTN_V_OFF (ATTN_K_OFF + 256 * AP)
#define ATTN_SMEM  (ATTN_V_OFF + 256 * AP)       // 92160 B

__global__ void __launch_bounds__(256, 2)
attn_tc(const __half* __restrict__ Q, const __half* __restrict__ K,
        const __half* __restrict__ V, __half* __restrict__ AO)
{
    extern __shared__ __align__(128) char sm[];
    const uint32_t sb = smem_to_u32(sm);

    const int h = blockIdx.x;
    const int n = blockIdx.y;
    const int b = blockIdx.z;
    const int tid = threadIdx.x;
    const int w = tid >> 5;
    const int lane = tid & 31;

    const size_t rowbase = (size_t)b * SS + (size_t)n * STEP;
    const int kcnt = (n == NB - 1) ? 128 : 256;

    const __half* Qg = Q + rowbase * DD + h * HD;
    const __half* Kg = K + rowbase * DD + h * HD;
    const __half* Vg = V + rowbase * DD + h * HD;
    for (int idx = tid; idx < 128 * 8; idx += 256) {
        int r = idx >> 3, c = idx & 7;
        *(uint4*)(sm + ATTN_Q_OFF + r * AP + c * 16) =
            *(const uint4*)(Qg + (size_t)r * DD + c * 8);
    }
    for (int idx = tid; idx < kcnt * 8; idx += 256) {
        int r = idx >> 3, c = idx & 7;
        *(uint4*)(sm + ATTN_K_OFF + r * AP + c * 16) =
            *(const uint4*)(Kg + (size_t)r * DD + c * 8);
        *(uint4*)(sm + ATTN_V_OFF + r * AP + c * 16) =
            *(const uint4*)(Vg + (size_t)r * DD + c * 8);
    }
    __syncthreads();

    uint32_t qf[4][4];
    {
        const uint32_t a_row = (uint32_t)(w * 16 + (lane & 15));
        const uint32_t a_sel = (uint32_t)(lane >> 4);
        #pragma unroll
        for (int t = 0; t < 4; t++)
            ldsm_x4(qf[t], sb + ATTN_Q_OFF + a_row * AP + (2 * t + a_sel) * 16);
    }

    float oacc[8][4];
    #pragma unroll
    for (int j = 0; j < 8; j++)
        #pragma unroll
        for (int e = 0; e < 4; e++) oacc[j][e] = 0.f;
    float rs_lo = 0.f, rs_hi = 0.f;

    const uint32_t b_row = (uint32_t)((lane & 7) + ((lane >> 4) << 3));
    const uint32_t b_sel = (uint32_t)((lane >> 3) & 1);
    const uint32_t v_row = (uint32_t)((lane & 7) + (((lane >> 3) & 1) << 3));
    const uint32_t v_col = (uint32_t)(((lane >> 4) & 1) << 4);

    const int nch = kcnt >> 6;
    for (int ch = 0; ch < nch; ch++) {
        const int kb = ch * 64;

        float sacc[8][4];
        #pragma unroll
        for (int j = 0; j < 8; j++)
            #pragma unroll
            for (int e = 0; e < 4; e++) sacc[j][e] = 0.f;

        #pragma unroll
        for (int g = 0; g < 4; g++) {
            #pragma unroll
            for (int t = 0; t < 4; t++) {
                uint32_t kf[4];
                ldsm_x4(kf, sb + ATTN_K_OFF + (kb + g * 16 + b_row) * AP
                              + (2 * t + b_sel) * 16);
                mma16816h(sacc[2 * g],     qf[t], &kf[0]);
                mma16816h(sacc[2 * g + 1], qf[t], &kf[2]);
            }
        }

        uint32_t pa[4][4];
        #pragma unroll
        for (int j = 0; j < 8; j++) {
            float p0 = __expf(sacc[j][0] * 0.125f);
            float p1 = __expf(sacc[j][1] * 0.125f);
            float p2 = __expf(sacc[j][2] * 0.125f);
            float p3 = __expf(sacc[j][3] * 0.125f);
            rs_lo += p0 + p1;
            rs_hi += p2 + p3;
            pa[j >> 1][(j & 1) * 2 + 0] = h2u(p0, p1);
            pa[j >> 1][(j & 1) * 2 + 1] = h2u(p2, p3);
        }

        #pragma unroll
        for (int t = 0; t < 4; t++) {
            #pragma unroll
            for (int dp = 0; dp < 4; dp++) {
                uint32_t vf[4];
                ldsm_x4_t(vf, sb + ATTN_V_OFF + (kb + t * 16 + v_row) * AP
                                + dp * 32 + v_col);
                mma16816h(oacc[2 * dp],     pa[t], &vf[0]);
                mma16816h(oacc[2 * dp + 1], pa[t], &vf[2]);
            }
        }
    }

    rs_lo += __shfl_xor_sync(0xffffffffu, rs_lo, 1);
    rs_lo += __shfl_xor_sync(0xffffffffu, rs_lo, 2);
    rs_hi += __shfl_xor_sync(0xffffffffu, rs_hi, 1);
    rs_hi += __shfl_xor_sync(0xffffffffu, rs_hi, 2);
    const float il = 1.f / rs_lo;
    const float ih = 1.f / rs_hi;

    const size_t row = rowbase + w * 16 + (lane >> 2);
    const int col0 = h * HD + (lane & 3) * 2;
    #pragma unroll
    for (int j = 0; j < 8; j++) {
        int c = col0 + j * 8;
        *(__half2*)(AO + row * DD + c) =
            __floats2half2_rn(oacc[j][0] * il, oacc[j][1] * il);
        *(__half2*)(AO + (row + 8) * DD + c) =
            __floats2half2_rn(oacc[j][2] * ih, oacc[j][3] * ih);
    }
}

// ---------------------------------------------------------------------------
// Residual add + LayerNorm
// ---------------------------------------------------------------------------
__global__ void __launch_bounds__(256)
ln_kernel(const float* __restrict__ hid, const float* __restrict__ proj,
          const float* __restrict__ w, const float* __restrict__ bb,
          float* __restrict__ out)
{
    const int row = blockIdx.x;
    const int tid = threadIdx.x;

    float4 hv = *(const float4*)(hid  + (size_t)row * DD + tid * 4);
    float4 pv = *(const float4*)(proj + (size_t)row * DD + tid * 4);
    float x0 = hv.x + pv.x, x1 = hv.y + pv.y, x2 = hv.z + pv.z, x3 = hv.w + pv.w;

    __shared__ float red1[8];
    __shared__ float red2[8];

    float s = x0 + x1 + x2 + x3;
    #pragma unroll
    for (int off = 16; off > 0; off >>= 1) s += __shfl_xor_sync(0xffffffffu, s, off);
    if ((tid & 31) == 0) red1[tid >> 5] = s;
    __syncthreads();
    float tot = red1[0] + red1[1] + red1[2] + red1[3]
              + red1[4] + red1[5] + red1[6] + red1[7];
    float mean = tot * (1.f / DD);

    float d0 = x0 - mean, d1 = x1 - mean, d2 = x2 - mean, d3 = x3 - mean;
    float s2 = d0*d0 + d1*d1 + d2*d2 + d3*d3;
    #pragma unroll
    for (int off = 16; off > 0; off >>= 1) s2 += __shfl_xor_sync(0xffffffffu, s2, off);
    if ((tid & 31) == 0) red2[tid >> 5] = s2;
    __syncthreads();
    float tot2 = red2[0] + red2[1] + red2[2] + red2[3]
               + red2[4] + red2[5] + red2[6] + red2[7];
    float rstd = rsqrtf(tot2 * (1.f / DD) + 1e-5f);

    float4 wv = *(const float4*)(w  + tid * 4);
    float4 bv = *(const float4*)(bb + tid * 4);
    float4 ov;
    ov.x = d0 * rstd * wv.x + bv.x;
    ov.y = d1 * rstd * wv.y + bv.y;
    ov.z = d2 * rstd * wv.z + bv.z;
    ov.w = d3 * rstd * wv.w + bv.w;
    *(float4*)(out + (size_t)row * DD + tid * 4) = ov;
}

// ---------------------------------------------------------------------------
extern "C" void kernel_launch(void* const* d_in, const int* in_sizes, int n_in,
                              void* d_out, int out_size)
{
    const float* hid = (const float*)d_in[0];
    const float* Wq  = (const float*)d_in[1];
    const float* bq  = (const float*)d_in[2];
    const float* Wk  = (const float*)d_in[3];
    const float* bk  = (const float*)d_in[4];
    const float* Wv  = (const float*)d_in[5];
    const float* bv  = (const float*)d_in[6];
    const float* Wo  = (const float*)d_in[7];
    const float* bo  = (const float*)d_in[8];
    const float* lnw = (const float*)d_in[9];
    const float* lnb = (const float*)d_in[10];
    float* out = (float*)d_out;

    __half *Qh, *Kh, *Vh, *AOh;
    float *Pb;
    cudaGetSymbolAddress((void**)&Qh,  g_Qh);
    cudaGetSymbolAddress((void**)&Kh,  g_Kh);
    cudaGetSymbolAddress((void**)&Vh,  g_Vh);
    cudaGetSymbolAddress((void**)&AOh, g_AOh);
    cudaGetSymbolAddress((void**)&Pb,  g_P);

    __half *hidh, *wqt, *wkt, *wvt, *wot;
    cudaGetSymbolAddress((void**)&hidh, g_hidh);
    cudaGetSymbolAddress((void**)&wqt,  g_wqt);
    cudaGetSymbolAddress((void**)&wkt,  g_wkt);
    cudaGetSymbolAddress((void**)&wvt,  g_wvt);
    cudaGetSymbolAddress((void**)&wot,  g_wot);

    static bool attr_set = false;
    if (!attr_set) {
        cudaFuncSetAttribute(attn_tc,
                             cudaFuncAttributeMaxDynamicSharedMemorySize, ATTN_SMEM);
        cudaFuncSetAttribute(gemm_qkv,
                             cudaFuncAttributeMaxDynamicSharedMemorySize, GEMM_SMEM);
        cudaFuncSetAttribute(gemm_h,
                             cudaFuncAttributeMaxDynamicSharedMemorySize, GEMM_SMEM);
        attr_set = true;
    }

    // fp16 conversions: hidden states + all 4 weights (single fused launch)
    cvt_h<<<MM * DD / (256 * 8), 256>>>(hid, hidh);
    dim3 tg(32, 32, 4);
    cvt_h_T4<<<tg, 256>>>(Wq, Wk, Wv, Wo, wqt, wkt, wvt, wot);

    // Fused Q/K/V projections (fp16 HMMA, fp16 out), 128x256 tiles
    dim3 gq(DD / 256, MM / 128, 3);  // (4, 64, 3)
    gemm_qkv<<<gq, 256, GEMM_SMEM>>>(hidh, wqt, wkt, wvt, bq, bk, bv, Qh, Kh, Vh);

    // Tensor-core attention (fp16 in/out), 2 CTAs/SM
    dim3 ag(HH, NB, BB);             // (16, 32, 2)
    attn_tc<<<ag, 256, ATTN_SMEM>>>(Qh, Kh, Vh, AOh);

    // O projection (fp32 out)
    dim3 gg(DD / 256, MM / 128);     // (4, 64)
    gemm_h<<<gg, 256, GEMM_SMEM>>>(AOh, wot, bo, Pb);

    // Residual + LayerNorm
    ln_kernel<<<MM, 256>>>(hid, Pb, lnw, lnb, out);
}

// round 15
// speedup vs baseline: 1.1018x; 1.0946x over previous
#include <cuda_runtime.h>
#include <cuda_fp16.h>
#include <cstdint>

// Problem constants
#define BB   2
#define SS   4096
#define DD   1024
#define HH   16
#define HD   64
#define NB   32           // S / STEP
#define STEP 128
#define MM   (BB*SS)      // 8192 rows

// ---------------------------------------------------------------------------
// Scratch (static device globals; no allocation)
// ---------------------------------------------------------------------------
__device__ __half g_Qh[MM*DD];
__device__ __half g_Kh[MM*DD];
__device__ __half g_Vh[MM*DD];
__device__ __half g_AOh[MM*DD];
__device__ float  g_P [MM*DD];

__device__ __half g_hidh[MM*DD];
// Transposed weights [n,k], fp16
__device__ __half g_wqt[DD*DD];
__device__ __half g_wkt[DD*DD];
__device__ __half g_wvt[DD*DD];
__device__ __half g_wot[DD*DD];

// ---------------------------------------------------------------------------
// Helpers
// ---------------------------------------------------------------------------
__device__ __forceinline__ uint32_t smem_to_u32(const void* smem_ptr) {
    uint32_t addr;
    asm("{ .reg .u64 tmp; cvta.to.shared.u64 tmp, %1; cvt.u32.u64 %0, tmp; }"
        : "=r"(addr) : "l"(smem_ptr));
    return addr;
}

__device__ __forceinline__ void cp16(uint32_t dst, const void* src) {
    asm volatile("cp.async.cg.shared.global [%0], [%1], 16;\n" :: "r"(dst), "l"(src) : "memory");
}

__device__ __forceinline__ void ldsm_x4(uint32_t* r, uint32_t addr) {
    asm volatile("ldmatrix.sync.aligned.m8n8.x4.shared.b16 {%0,%1,%2,%3}, [%4];"
        : "=r"(r[0]), "=r"(r[1]), "=r"(r[2]), "=r"(r[3]) : "r"(addr));
}

__device__ __forceinline__ void ldsm_x4_t(uint32_t* r, uint32_t addr) {
    asm volatile("ldmatrix.sync.aligned.m8n8.x4.trans.shared.b16 {%0,%1,%2,%3}, [%4];"
        : "=r"(r[0]), "=r"(r[1]), "=r"(r[2]), "=r"(r[3]) : "r"(addr));
}

// D += A*B  (m16n8k16, fp16 in, fp32 accum)
__device__ __forceinline__ void mma16816h(float* d, const uint32_t* a, const uint32_t* b) {
    asm volatile(
        "mma.sync.aligned.m16n8k16.row.col.f32.f16.f16.f32 "
        "{%0,%1,%2,%3}, {%4,%5,%6,%7}, {%8,%9}, {%0,%1,%2,%3};"
        : "+f"(d[0]), "+f"(d[1]), "+f"(d[2]), "+f"(d[3])
        : "r"(a[0]), "r"(a[1]), "r"(a[2]), "r"(a[3]), "r"(b[0]), "r"(b[1]));
}

__device__ __forceinline__ uint32_t h2u(float a, float b) {
    __half2 h = __floats2half2_rn(a, b);
    return *(uint32_t*)&h;
}

// ---------------------------------------------------------------------------
// Conversion kernels: fp32 -> fp16
// ---------------------------------------------------------------------------
__global__ void __launch_bounds__(256)
cvt_h(const float* __restrict__ x, __half* __restrict__ y)
{
    int i = (blockIdx.x * 256 + threadIdx.x) * 8;
    float4 v0 = *(const float4*)(x + i);
    float4 v1 = *(const float4*)(x + i + 4);
    __half2* yp = (__half2*)(y + i);
    yp[0] = __floats2half2_rn(v0.x, v0.y);
    yp[1] = __floats2half2_rn(v0.z, v0.w);
    yp[2] = __floats2half2_rn(v1.x, v1.y);
    yp[3] = __floats2half2_rn(v1.z, v1.w);
}

// All 4 weights [K,N] -> [n,k] fp16 (transposed), one launch, grid.z selects.
__global__ void __launch_bounds__(256)
cvt_h_T4(const float* __restrict__ W0, const float* __restrict__ W1,
         const float* __restrict__ W2, const float* __restrict__ W3,
         __half* __restrict__ T0, __half* __restrict__ T1,
         __half* __restrict__ T2, __half* __restrict__ T3)
{
    const int z = blockIdx.z;
    const float* W = (z == 0) ? W0 : (z == 1) ? W1 : (z == 2) ? W2 : W3;
    __half*      T = (z == 0) ? T0 : (z == 1) ? T1 : (z == 2) ? T2 : T3;

    __shared__ float t[32][33];
    int tx = threadIdx.x & 31, ty = threadIdx.x >> 5;  // ty 0..7
    int n0 = blockIdx.x * 32, k0 = blockIdx.y * 32;
    #pragma unroll
    for (int r = ty; r < 32; r += 8)
        t[r][tx] = W[(size_t)(k0 + r) * DD + n0 + tx];
    __syncthreads();
    #pragma unroll
    for (int r = ty; r < 32; r += 8)
        T[(size_t)(n0 + r) * DD + k0 + tx] = __float2half_rn(t[tx][r]);
}

// ---------------------------------------------------------------------------
// HMMA GEMM core (R9 config — measured at the mma.sync issue ceiling):
// 128x128 tile, BK=64, 2-stage cp.async double buffer, 8 warps (64x32/warp),
// pitch 144 B (conflict-free), 2 CTAs/SM.
// ---------------------------------------------------------------------------
#define NCH 16                      // 1024 / 64
#define GP  144                     // smem row pitch (9 x 16B)
#define GB_OFF (128 * GP)           // B tile offset inside stage
#define GSTAGE (256 * GP)           // 36864 B
#define GEMM_SMEM (2 * GSTAGE)      // 73728 B -> 2 CTAs/SM

__device__ __forceinline__ void load_stage(
    uint32_t sbase,
    const __half* __restrict__ A, const __half* __restrict__ B,
    int block_row, int block_col, int k0, int tid)
{
    #pragma unroll
    for (int t = 0; t < 4; t++) {
        int idx = tid + t * 256;   // 0..1023
        int r = idx >> 3;          // 0..127
        int c = idx & 7;           // 16B chunk within 128B row
        uint32_t soff = (uint32_t)(r * GP + c * 16);
        cp16(sbase +          soff, A + (size_t)(block_row + r) * DD + k0 + c * 8);
        cp16(sbase + GB_OFF + soff, B + (size_t)(block_col + r) * DD + k0 + c * 8);
    }
    asm volatile("cp.async.commit_group;\n" ::: "memory");
}

// Mainloop computing acc[4][4][4] for a 128x128 tile.
__device__ __forceinline__ void gemm_main(
    float acc[4][4][4], uint32_t smem_base,
    const __half* __restrict__ A, const __half* __restrict__ B,
    int block_row, int block_col, int tid)
{
    const int wid  = tid >> 5;
    const int lane = tid & 31;
    const int wm = wid >> 2;
    const int wn = wid & 3;

    load_stage(smem_base, A, B, block_row, block_col, 0, tid);

    const uint32_t a_row = (uint32_t)(wm * 64 + (lane & 15));
    const uint32_t a_sel = (uint32_t)(lane >> 4);
    const uint32_t b_row = (uint32_t)(wn * 32 + (lane & 7) + ((lane >> 4) << 3));
    const uint32_t b_sel = (uint32_t)((lane >> 3) & 1);

    for (int cc = 0; cc < NCH; cc++) {
        asm volatile("cp.async.wait_group 0;\n" ::: "memory");
        __syncthreads();

        if (cc + 1 < NCH)
            load_stage(smem_base + ((cc + 1) & 1) * GSTAGE,
                       A, B, block_row, block_col, (cc + 1) * 64, tid);

        const uint32_t sb = smem_base + (cc & 1) * GSTAGE;

        #pragma unroll
        for (int ks = 0; ks < 4; ks++) {
            const uint32_t ach = (2 * ks + a_sel) * 16;
            const uint32_t bch = (2 * ks + b_sel) * 16;

            uint32_t af[4][4];
            #pragma unroll
            for (int mt = 0; mt < 4; mt++)
                ldsm_x4(af[mt], sb + (a_row + mt * 16) * GP + ach);
            uint32_t bf[2][4];
            #pragma unroll
            for (int g = 0; g < 2; g++)
                ldsm_x4(bf[g], sb + GB_OFF + (b_row + g * 16) * GP + bch);

            #pragma unroll
            for (int mt = 0; mt < 4; mt++)
                #pragma unroll
                for (int nt = 0; nt < 4; nt++)
                    mma16816h(acc[mt][nt], af[mt], &bf[nt >> 1][(nt & 1) * 2]);
        }
    }
}

// Fused QKV GEMM: fp16 output. grid.z selects weight/bias/output.
__global__ void __launch_bounds__(256, 2)
gemm_qkv(const __half* __restrict__ A,
         const __half* __restrict__ Bq, const __half* __restrict__ Bk,
         const __half* __restrict__ Bv,
         const float* __restrict__ bq, const float* __restrict__ bk,
         const float* __restrict__ bv,
         __half* __restrict__ Cq, __half* __restrict__ Ck, __half* __restrict__ Cv)
{
    extern __shared__ __align__(128) char smem[];
    const int z = blockIdx.z;
    const __half* B = (z == 0) ? Bq : (z == 1) ? Bk : Bv;
    const float* bias = (z == 0) ? bq : (z == 1) ? bk : bv;
    __half* C = (z == 0) ? Cq : (z == 1) ? Ck : Cv;

    const int tid = threadIdx.x;
    const int block_col = blockIdx.x * 128;
    const int block_row = blockIdx.y * 128;

    float acc[4][4][4];
    #pragma unroll
    for (int i = 0; i < 4; i++)
        #pragma unroll
        for (int j = 0; j < 4; j++)
            #pragma unroll
            for (int e = 0; e < 4; e++) acc[i][j][e] = 0.f;

    gemm_main(acc, smem_to_u32(smem), A, B, block_row, block_col, tid);

    const int wid = tid >> 5, lane = tid & 31;
    const int row0 = block_row + (wid >> 2) * 64 + (lane >> 2);
    const int col0 = block_col + (wid & 3) * 32 + (lane & 3) * 2;
    #pragma unroll
    for (int mt = 0; mt < 4; mt++) {
        int r = row0 + mt * 16;
        #pragma unroll
        for (int nt = 0; nt < 4; nt++) {
            int ccol = col0 + nt * 8;
            float2 bv2 = *(const float2*)(bias + ccol);
            __half2 v0 = __floats2half2_rn(acc[mt][nt][0] + bv2.x, acc[mt][nt][1] + bv2.y);
            __half2 v1 = __floats2half2_rn(acc[mt][nt][2] + bv2.x, acc[mt][nt][3] + bv2.y);
            *(__half2*)(C + (size_t)r * DD + ccol)       = v0;
            *(__half2*)(C + (size_t)(r + 8) * DD + ccol) = v1;
        }
    }
}

// O-projection GEMM: fp32 output.
__global__ void __launch_bounds__(256, 2)
gemm_h(const __half* __restrict__ A, const __half* __restrict__ B,
       const float* __restrict__ bias, float* __restrict__ C)
{
    extern __shared__ __align__(128) char smem[];
    const int tid = threadIdx.x;
    const int block_col = blockIdx.x * 128;
    const int block_row = blockIdx.y * 128;

    float acc[4][4][4];
    #pragma unroll
    for (int i = 0; i < 4; i++)
        #pragma unroll
        for (int j = 0; j < 4; j++)
            #pragma unroll
            for (int e = 0; e < 4; e++) acc[i][j][e] = 0.f;

    gemm_main(acc, smem_to_u32(smem), A, B, block_row, block_col, tid);

    const int wid = tid >> 5, lane = tid & 31;
    const int row0 = block_row + (wid >> 2) * 64 + (lane >> 2);
    const int col0 = block_col + (wid & 3) * 32 + (lane & 3) * 2;
    #pragma unroll
    for (int mt = 0; mt < 4; mt++) {
        int r = row0 + mt * 16;
        #pragma unroll
        for (int nt = 0; nt < 4; nt++) {
            int ccol = col0 + nt * 8;
            float2 bv = *(const float2*)(bias + ccol);
            float2 v0 = { acc[mt][nt][0] + bv.x, acc[mt][nt][1] + bv.y };
            float2 v1 = { acc[mt][nt][2] + bv.x, acc[mt][nt][3] + bv.y };
            *(float2*)(C + (size_t)r * DD + ccol)       = v0;
            *(float2*)(C + (size_t)(r + 8) * DD + ccol) = v1;
        }
    }
}

// ---------------------------------------------------------------------------
// Tensor-core attention. One CTA per (b, h, n): 128 queries x kcnt keys.
// 8 warps x 16 query rows. K processed in chunks of 64 keys. 2 CTAs/SM.
// S-loop ordered t-outer/g-inner: accumulator reuse distance = 8 independent
// MMAs (was 2) -> hides HMMA RAW latency.
// ---------------------------------------------------------------------------
#define AP 144                                   // smem row pitch (bytes)
#define ATTN_Q_OFF 0
#define ATTN_K_OFF (128 * AP)
#define ATTN_V_OFF (ATTN_K_OFF + 256 * AP)
#define ATTN_SMEM  (ATTN_V_OFF + 256 * AP)       // 92160 B

__global__ void __launch_bounds__(256, 2)
attn_tc(const __half* __restrict__ Q, const __half* __restrict__ K,
        const __half* __restrict__ V, __half* __restrict__ AO)
{
    extern __shared__ __align__(128) char sm[];
    const uint32_t sb = smem_to_u32(sm);

    const int h = blockIdx.x;
    const int n = blockIdx.y;
    const int b = blockIdx.z;
    const int tid = threadIdx.x;
    const int w = tid >> 5;
    const int lane = tid & 31;

    const size_t rowbase = (size_t)b * SS + (size_t)n * STEP;
    const int kcnt = (n == NB - 1) ? 128 : 256;

    const __half* Qg = Q + rowbase * DD + h * HD;
    const __half* Kg = K + rowbase * DD + h * HD;
    const __half* Vg = V + rowbase * DD + h * HD;
    for (int idx = tid; idx < 128 * 8; idx += 256) {
        int r = idx >> 3, c = idx & 7;
        *(uint4*)(sm + ATTN_Q_OFF + r * AP + c * 16) =
            *(const uint4*)(Qg + (size_t)r * DD + c * 8);
    }
    for (int idx = tid; idx < kcnt * 8; idx += 256) {
        int r = idx >> 3, c = idx & 7;
        *(uint4*)(sm + ATTN_K_OFF + r * AP + c * 16) =
            *(const uint4*)(Kg + (size_t)r * DD + c * 8);
        *(uint4*)(sm + ATTN_V_OFF + r * AP + c * 16) =
            *(const uint4*)(Vg + (size_t)r * DD + c * 8);
    }
    __syncthreads();

    uint32_t qf[4][4];
    {
        const uint32_t a_row = (uint32_t)(w * 16 + (lane & 15));
        const uint32_t a_sel = (uint32_t)(lane >> 4);
        #pragma unroll
        for (int t = 0; t < 4; t++)
            ldsm_x4(qf[t], sb + ATTN_Q_OFF + a_row * AP + (2 * t + a_sel) * 16);
    }

    float oacc[8][4];
    #pragma unroll
    for (int j = 0; j < 8; j++)
        #pragma unroll
        for (int e = 0; e < 4; e++) oacc[j][e] = 0.f;
    float rs_lo = 0.f, rs_hi = 0.f;

    const uint32_t b_row = (uint32_t)((lane & 7) + ((lane >> 4) << 3));
    const uint32_t b_sel = (uint32_t)((lane >> 3) & 1);
    const uint32_t v_row = (uint32_t)((lane & 7) + (((lane >> 3) & 1) << 3));
    const uint32_t v_col = (uint32_t)(((lane >> 4) & 1) << 4);

    const int nch = kcnt >> 6;
    for (int ch = 0; ch < nch; ch++) {
        const int kb = ch * 64;

        float sacc[8][4];
        #pragma unroll
        for (int j = 0; j < 8; j++)
            #pragma unroll
            for (int e = 0; e < 4; e++) sacc[j][e] = 0.f;

        // t outer, g inner: 8 independent MMAs between accumulator reuses
        #pragma unroll
        for (int t = 0; t < 4; t++) {
            #pragma unroll
            for (int g = 0; g < 4; g++) {
                uint32_t kf[4];
                ldsm_x4(kf, sb + ATTN_K_OFF + (kb + g * 16 + b_row) * AP
                              + (2 * t + b_sel) * 16);
                mma16816h(sacc[2 * g],     qf[t], &kf[0]);
                mma16816h(sacc[2 * g + 1], qf[t], &kf[2]);
            }
        }

        uint32_t pa[4][4];
        #pragma unroll
        for (int j = 0; j < 8; j++) {
            float p0 = __expf(sacc[j][0] * 0.125f);
            float p1 = __expf(sacc[j][1] * 0.125f);
            float p2 = __expf(sacc[j][2] * 0.125f);
            float p3 = __expf(sacc[j][3] * 0.125f);
            rs_lo += p0 + p1;
            rs_hi += p2 + p3;
            pa[j >> 1][(j & 1) * 2 + 0] = h2u(p0, p1);
            pa[j >> 1][(j & 1) * 2 + 1] = h2u(p2, p3);
        }

        #pragma unroll
        for (int t = 0; t < 4; t++) {
            #pragma unroll
            for (int dp = 0; dp < 4; dp++) {
                uint32_t vf[4];
                ldsm_x4_t(vf, sb + ATTN_V_OFF + (kb + t * 16 + v_row) * AP
                                + dp * 32 + v_col);
                mma16816h(oacc[2 * dp],     pa[t], &vf[0]);
                mma16816h(oacc[2 * dp + 1], pa[t], &vf[2]);
            }
        }
    }

    rs_lo += __shfl_xor_sync(0xffffffffu, rs_lo, 1);
    rs_lo += __shfl_xor_sync(0xffffffffu, rs_lo, 2);
    rs_hi += __shfl_xor_sync(0xffffffffu, rs_hi, 1);
    rs_hi += __shfl_xor_sync(0xffffffffu, rs_hi, 2);
    const float il = 1.f / rs_lo;
    const float ih = 1.f / rs_hi;

    const size_t row = rowbase + w * 16 + (lane >> 2);
    const int col0 = h * HD + (lane & 3) * 2;
    #pragma unroll
    for (int j = 0; j < 8; j++) {
        int c = col0 + j * 8;
        *(__half2*)(AO + row * DD + c) =
            __floats2half2_rn(oacc[j][0] * il, oacc[j][1] * il);
        *(__half2*)(AO + (row + 8) * DD + c) =
            __floats2half2_rn(oacc[j][2] * ih, oacc[j][3] * ih);
    }
}

// ---------------------------------------------------------------------------
// Residual add + LayerNorm
// ---------------------------------------------------------------------------
__global__ void __launch_bounds__(256)
ln_kernel(const float* __restrict__ hid, const float* __restrict__ proj,
          const float* __restrict__ w, const float* __restrict__ bb,
          float* __restrict__ out)
{
    const int row = blockIdx.x;
    const int tid = threadIdx.x;

    float4 hv = *(const float4*)(hid  + (size_t)row * DD + tid * 4);
    float4 pv = *(const float4*)(proj + (size_t)row * DD + tid * 4);
    float x0 = hv.x + pv.x, x1 = hv.y + pv.y, x2 = hv.z + pv.z, x3 = hv.w + pv.w;

    __shared__ float red1[8];
    __shared__ float red2[8];

    float s = x0 + x1 + x2 + x3;
    #pragma unroll
    for (int off = 16; off > 0; off >>= 1) s += __shfl_xor_sync(0xffffffffu, s, off);
    if ((tid & 31) == 0) red1[tid >> 5] = s;
    __syncthreads();
    float tot = red1[0] + red1[1] + red1[2] + red1[3]
              + red1[4] + red1[5] + red1[6] + red1[7];
    float mean = tot * (1.f / DD);

    float d0 = x0 - mean, d1 = x1 - mean, d2 = x2 - mean, d3 = x3 - mean;
    float s2 = d0*d0 + d1*d1 + d2*d2 + d3*d3;
    #pragma unroll
    for (int off = 16; off > 0; off >>= 1) s2 += __shfl_xor_sync(0xffffffffu, s2, off);
    if ((tid & 31) == 0) red2[tid >> 5] = s2;
    __syncthreads();
    float tot2 = red2[0] + red2[1] + red2[2] + red2[3]
               + red2[4] + red2[5] + red2[6] + red2[7];
    float rstd = rsqrtf(tot2 * (1.f / DD) + 1e-5f);

    float4 wv = *(const float4*)(w  + tid * 4);
    float4 bv = *(const float4*)(bb + tid * 4);
    float4 ov;
    ov.x = d0 * rstd * wv.x + bv.x;
    ov.y = d1 * rstd * wv.y + bv.y;
    ov.z = d2 * rstd * wv.z + bv.z;
    ov.w = d3 * rstd * wv.w + bv.w;
    *(float4*)(out + (size_t)row * DD + tid * 4) = ov;
}

// ---------------------------------------------------------------------------
extern "C" void kernel_launch(void* const* d_in, const int* in_sizes, int n_in,
                              void* d_out, int out_size)
{
    const float* hid = (const float*)d_in[0];
    const float* Wq  = (const float*)d_in[1];
    const float* bq  = (const float*)d_in[2];
    const float* Wk  = (const float*)d_in[3];
    const float* bk  = (const float*)d_in[4];
    const float* Wv  = (const float*)d_in[5];
    const float* bv  = (const float*)d_in[6];
    const float* Wo  = (const float*)d_in[7];
    const float* bo  = (const float*)d_in[8];
    const float* lnw = (const float*)d_in[9];
    const float* lnb = (const float*)d_in[10];
    float* out = (float*)d_out;

    __half *Qh, *Kh, *Vh, *AOh;
    float *Pb;
    cudaGetSymbolAddress((void**)&Qh,  g_Qh);
    cudaGetSymbolAddress((void**)&Kh,  g_Kh);
    cudaGetSymbolAddress((void**)&Vh,  g_Vh);
    cudaGetSymbolAddress((void**)&AOh, g_AOh);
    cudaGetSymbolAddress((void**)&Pb,  g_P);

    __half *hidh, *wqt, *wkt, *wvt, *wot;
    cudaGetSymbolAddress((void**)&hidh, g_hidh);
    cudaGetSymbolAddress((void**)&wqt,  g_wqt);
    cudaGetSymbolAddress((void**)&wkt,  g_wkt);
    cudaGetSymbolAddress((void**)&wvt,  g_wvt);
    cudaGetSymbolAddress((void**)&wot,  g_wot);

    static bool attr_set = false;
    if (!attr_set) {
        cudaFuncSetAttribute(attn_tc,
                             cudaFuncAttributeMaxDynamicSharedMemorySize, ATTN_SMEM);
        cudaFuncSetAttribute(gemm_qkv,
                             cudaFuncAttributeMaxDynamicSharedMemorySize, GEMM_SMEM);
        cudaFuncSetAttribute(gemm_h,
                             cudaFuncAttributeMaxDynamicSharedMemorySize, GEMM_SMEM);
        attr_set = true;
    }

    // fp16 conversions: hidden states + all 4 weights (single fused launch)
    cvt_h<<<MM * DD / (256 * 8), 256>>>(hid, hidh);
    dim3 tg(32, 32, 4);
    cvt_h_T4<<<tg, 256>>>(Wq, Wk, Wv, Wo, wqt, wkt, wvt, wot);

    // Fused Q/K/V projections (fp16 HMMA, fp16 out)
    dim3 gq(DD / 128, MM / 128, 3);  // (8, 64, 3)
    gemm_qkv<<<gq, 256, GEMM_SMEM>>>(hidh, wqt, wkt, wvt, bq, bk, bv, Qh, Kh, Vh);

    // Tensor-core attention (fp16 in/out), 2 CTAs/SM
    dim3 ag(HH, NB, BB);             // (16, 32, 2)
    attn_tc<<<ag, 256, ATTN_SMEM>>>(Qh, Kh, Vh, AOh);

    // O projection (fp32 out)
    dim3 gg(DD / 128, MM / 128);     // (8, 64)
    gemm_h<<<gg, 256, GEMM_SMEM>>>(AOh, wot, bo, Pb);

    // Residual + LayerNorm
    ln_kernel<<<MM, 256>>>(hid, Pb, lnw, lnb, out);
}

// round 16
// speedup vs baseline: 1.1054x; 1.0033x over previous
#include <cuda_runtime.h>
#include <cuda_fp16.h>
#include <cstdint>

// Problem constants
#define BB   2
#define SS   4096
#define DD   1024
#define HH   16
#define HD   64
#define NB   32           // S / STEP
#define STEP 128
#define MM   (BB*SS)      // 8192 rows

// ---------------------------------------------------------------------------
// Scratch (static device globals; no allocation)
// ---------------------------------------------------------------------------
__device__ __half g_Qh[MM*DD];
__device__ __half g_Kh[MM*DD];
__device__ __half g_Vh[MM*DD];
__device__ __half g_AOh[MM*DD];
__device__ float  g_P [MM*DD];

__device__ __half g_hidh[MM*DD];
// Transposed weights [n,k], fp16
__device__ __half g_wqt[DD*DD];
__device__ __half g_wkt[DD*DD];
__device__ __half g_wvt[DD*DD];
__device__ __half g_wot[DD*DD];

// ---------------------------------------------------------------------------
// Helpers
// ---------------------------------------------------------------------------
__device__ __forceinline__ uint32_t smem_to_u32(const void* smem_ptr) {
    uint32_t addr;
    asm("{ .reg .u64 tmp; cvta.to.shared.u64 tmp, %1; cvt.u32.u64 %0, tmp; }"
        : "=r"(addr) : "l"(smem_ptr));
    return addr;
}

__device__ __forceinline__ void cp16(uint32_t dst, const void* src) {
    asm volatile("cp.async.cg.shared.global [%0], [%1], 16;\n" :: "r"(dst), "l"(src) : "memory");
}

__device__ __forceinline__ void ldsm_x4(uint32_t* r, uint32_t addr) {
    asm volatile("ldmatrix.sync.aligned.m8n8.x4.shared.b16 {%0,%1,%2,%3}, [%4];"
        : "=r"(r[0]), "=r"(r[1]), "=r"(r[2]), "=r"(r[3]) : "r"(addr));
}

__device__ __forceinline__ void ldsm_x4_t(uint32_t* r, uint32_t addr) {
    asm volatile("ldmatrix.sync.aligned.m8n8.x4.trans.shared.b16 {%0,%1,%2,%3}, [%4];"
        : "=r"(r[0]), "=r"(r[1]), "=r"(r[2]), "=r"(r[3]) : "r"(addr));
}

// D += A*B  (m16n8k16, fp16 in, fp32 accum)
__device__ __forceinline__ void mma16816h(float* d, const uint32_t* a, const uint32_t* b) {
    asm volatile(
        "mma.sync.aligned.m16n8k16.row.col.f32.f16.f16.f32 "
        "{%0,%1,%2,%3}, {%4,%5,%6,%7}, {%8,%9}, {%0,%1,%2,%3};"
        : "+f"(d[0]), "+f"(d[1]), "+f"(d[2]), "+f"(d[3])
        : "r"(a[0]), "r"(a[1]), "r"(a[2]), "r"(a[3]), "r"(b[0]), "r"(b[1]));
}

__device__ __forceinline__ uint32_t h2u(float a, float b) {
    __half2 h = __floats2half2_rn(a, b);
    return *(uint32_t*)&h;
}

// ---------------------------------------------------------------------------
// Conversion kernels: fp32 -> fp16
// ---------------------------------------------------------------------------
__global__ void __launch_bounds__(256)
cvt_h(const float* __restrict__ x, __half* __restrict__ y)
{
    int i = (blockIdx.x * 256 + threadIdx.x) * 8;
    float4 v0 = *(const float4*)(x + i);
    float4 v1 = *(const float4*)(x + i + 4);
    __half2* yp = (__half2*)(y + i);
    yp[0] = __floats2half2_rn(v0.x, v0.y);
    yp[1] = __floats2half2_rn(v0.z, v0.w);
    yp[2] = __floats2half2_rn(v1.x, v1.y);
    yp[3] = __floats2half2_rn(v1.z, v1.w);
}

// All 4 weights [K,N] -> [n,k] fp16 (transposed), one launch, grid.z selects.
__global__ void __launch_bounds__(256)
cvt_h_T4(const float* __restrict__ W0, const float* __restrict__ W1,
         const float* __restrict__ W2, const float* __restrict__ W3,
         __half* __restrict__ T0, __half* __restrict__ T1,
         __half* __restrict__ T2, __half* __restrict__ T3)
{
    const int z = blockIdx.z;
    const float* W = (z == 0) ? W0 : (z == 1) ? W1 : (z == 2) ? W2 : W3;
    __half*      T = (z == 0) ? T0 : (z == 1) ? T1 : (z == 2) ? T2 : T3;

    __shared__ float t[32][33];
    int tx = threadIdx.x & 31, ty = threadIdx.x >> 5;  // ty 0..7
    int n0 = blockIdx.x * 32, k0 = blockIdx.y * 32;
    #pragma unroll
    for (int r = ty; r < 32; r += 8)
        t[r][tx] = W[(size_t)(k0 + r) * DD + n0 + tx];
    __syncthreads();
    #pragma unroll
    for (int r = ty; r < 32; r += 8)
        T[(size_t)(n0 + r) * DD + k0 + tx] = __float2half_rn(t[tx][r]);
}

// ---------------------------------------------------------------------------
// HMMA GEMM core (R9 config — measured at the mma.sync issue ceiling):
// 128x128 tile, BK=64, 2-stage cp.async double buffer, 8 warps (64x32/warp),
// pitch 144 B (conflict-free), 2 CTAs/SM.
// ---------------------------------------------------------------------------
#define NCH 16                      // 1024 / 64
#define GP  144                     // smem row pitch (9 x 16B)
#define GB_OFF (128 * GP)           // B tile offset inside stage
#define GSTAGE (256 * GP)           // 36864 B
#define GEMM_SMEM (2 * GSTAGE)      // 73728 B -> 2 CTAs/SM

__device__ __forceinline__ void load_stage(
    uint32_t sbase,
    const __half* __restrict__ A, const __half* __restrict__ B,
    int block_row, int block_col, int k0, int tid)
{
    #pragma unroll
    for (int t = 0; t < 4; t++) {
        int idx = tid + t * 256;   // 0..1023
        int r = idx >> 3;          // 0..127
        int c = idx & 7;           // 16B chunk within 128B row
        uint32_t soff = (uint32_t)(r * GP + c * 16);
        cp16(sbase +          soff, A + (size_t)(block_row + r) * DD + k0 + c * 8);
        cp16(sbase + GB_OFF + soff, B + (size_t)(block_col + r) * DD + k0 + c * 8);
    }
    asm volatile("cp.async.commit_group;\n" ::: "memory");
}

// Mainloop computing acc[4][4][4] for a 128x128 tile.
__device__ __forceinline__ void gemm_main(
    float acc[4][4][4], uint32_t smem_base,
    const __half* __restrict__ A, const __half* __restrict__ B,
    int block_row, int block_col, int tid)
{
    const int wid  = tid >> 5;
    const int lane = tid & 31;
    const int wm = wid >> 2;
    const int wn = wid & 3;

    load_stage(smem_base, A, B, block_row, block_col, 0, tid);

    const uint32_t a_row = (uint32_t)(wm * 64 + (lane & 15));
    const uint32_t a_sel = (uint32_t)(lane >> 4);
    const uint32_t b_row = (uint32_t)(wn * 32 + (lane & 7) + ((lane >> 4) << 3));
    const uint32_t b_sel = (uint32_t)((lane >> 3) & 1);

    for (int cc = 0; cc < NCH; cc++) {
        asm volatile("cp.async.wait_group 0;\n" ::: "memory");
        __syncthreads();

        if (cc + 1 < NCH)
            load_stage(smem_base + ((cc + 1) & 1) * GSTAGE,
                       A, B, block_row, block_col, (cc + 1) * 64, tid);

        const uint32_t sb = smem_base + (cc & 1) * GSTAGE;

        #pragma unroll
        for (int ks = 0; ks < 4; ks++) {
            const uint32_t ach = (2 * ks + a_sel) * 16;
            const uint32_t bch = (2 * ks + b_sel) * 16;

            uint32_t af[4][4];
            #pragma unroll
            for (int mt = 0; mt < 4; mt++)
                ldsm_x4(af[mt], sb + (a_row + mt * 16) * GP + ach);
            uint32_t bf[2][4];
            #pragma unroll
            for (int g = 0; g < 2; g++)
                ldsm_x4(bf[g], sb + GB_OFF + (b_row + g * 16) * GP + bch);

            #pragma unroll
            for (int mt = 0; mt < 4; mt++)
                #pragma unroll
                for (int nt = 0; nt < 4; nt++)
                    mma16816h(acc[mt][nt], af[mt], &bf[nt >> 1][(nt & 1) * 2]);
        }
    }
}

// Fused QKV GEMM: fp16 output. grid.z selects weight/bias/output.
__global__ void __launch_bounds__(256, 2)
gemm_qkv(const __half* __restrict__ A,
         const __half* __restrict__ Bq, const __half* __restrict__ Bk,
         const __half* __restrict__ Bv,
         const float* __restrict__ bq, const float* __restrict__ bk,
         const float* __restrict__ bv,
         __half* __restrict__ Cq, __half* __restrict__ Ck, __half* __restrict__ Cv)
{
    extern __shared__ __align__(128) char smem[];
    const int z = blockIdx.z;
    const __half* B = (z == 0) ? Bq : (z == 1) ? Bk : Bv;
    const float* bias = (z == 0) ? bq : (z == 1) ? bk : bv;
    __half* C = (z == 0) ? Cq : (z == 1) ? Ck : Cv;

    const int tid = threadIdx.x;
    const int block_col = blockIdx.x * 128;
    const int block_row = blockIdx.y * 128;

    float acc[4][4][4];
    #pragma unroll
    for (int i = 0; i < 4; i++)
        #pragma unroll
        for (int j = 0; j < 4; j++)
            #pragma unroll
            for (int e = 0; e < 4; e++) acc[i][j][e] = 0.f;

    gemm_main(acc, smem_to_u32(smem), A, B, block_row, block_col, tid);

    const int wid = tid >> 5, lane = tid & 31;
    const int row0 = block_row + (wid >> 2) * 64 + (lane >> 2);
    const int col0 = block_col + (wid & 3) * 32 + (lane & 3) * 2;
    #pragma unroll
    for (int mt = 0; mt < 4; mt++) {
        int r = row0 + mt * 16;
        #pragma unroll
        for (int nt = 0; nt < 4; nt++) {
            int ccol = col0 + nt * 8;
            float2 bv2 = *(const float2*)(bias + ccol);
            __half2 v0 = __floats2half2_rn(acc[mt][nt][0] + bv2.x, acc[mt][nt][1] + bv2.y);
            __half2 v1 = __floats2half2_rn(acc[mt][nt][2] + bv2.x, acc[mt][nt][3] + bv2.y);
            *(__half2*)(C + (size_t)r * DD + ccol)       = v0;
            *(__half2*)(C + (size_t)(r + 8) * DD + ccol) = v1;
        }
    }
}

// O-projection GEMM: fp32 output.
__global__ void __launch_bounds__(256, 2)
gemm_h(const __half* __restrict__ A, const __half* __restrict__ B,
       const float* __restrict__ bias, float* __restrict__ C)
{
    extern __shared__ __align__(128) char smem[];
    const int tid = threadIdx.x;
    const int block_col = blockIdx.x * 128;
    const int block_row = blockIdx.y * 128;

    float acc[4][4][4];
    #pragma unroll
    for (int i = 0; i < 4; i++)
        #pragma unroll
        for (int j = 0; j < 4; j++)
            #pragma unroll
            for (int e = 0; e < 4; e++) acc[i][j][e] = 0.f;

    gemm_main(acc, smem_to_u32(smem), A, B, block_row, block_col, tid);

    const int wid = tid >> 5, lane = tid & 31;
    const int row0 = block_row + (wid >> 2) * 64 + (lane >> 2);
    const int col0 = block_col + (wid & 3) * 32 + (lane & 3) * 2;
    #pragma unroll
    for (int mt = 0; mt < 4; mt++) {
        int r = row0 + mt * 16;
        #pragma unroll
        for (int nt = 0; nt < 4; nt++) {
            int ccol = col0 + nt * 8;
            float2 bv = *(const float2*)(bias + ccol);
            float2 v0 = { acc[mt][nt][0] + bv.x, acc[mt][nt][1] + bv.y };
            float2 v1 = { acc[mt][nt][2] + bv.x, acc[mt][nt][3] + bv.y };
            *(float2*)(C + (size_t)r * DD + ccol)       = v0;
            *(float2*)(C + (size_t)(r + 8) * DD + ccol) = v1;
        }
    }
}

// ---------------------------------------------------------------------------
// Tensor-core attention. One CTA per (b, h, n): 128 queries x kcnt keys.
// 8 warps x 16 query rows. K processed in chunks of 64 keys. 2 CTAs/SM.
// S-loop ordered t-outer/g-inner: accumulator reuse distance = 8 independent
// MMAs (was 2) -> hides HMMA RAW latency.
// ---------------------------------------------------------------------------
#define AP 144                                   // smem row pitch (bytes)
#define ATTN_Q_OFF 0
#define ATTN_K_OFF (128 * AP)
#define ATTN_V_OFF (ATTN_K_OFF + 256 * AP)
#define ATTN_SMEM  (ATTN_V_OFF + 256 * AP)       // 92160 B

__global__ void __launch_bounds__(256, 2)
attn_tc(const __half* __restrict__ Q, const __half* __restrict__ K,
        const __half* __restrict__ V, __half* __restrict__ AO)
{
    extern __shared__ __align__(128) char sm[];
    const uint32_t sb = smem_to_u32(sm);

    const int h = blockIdx.x;
    const int n = blockIdx.y;
    const int b = blockIdx.z;
    const int tid = threadIdx.x;
    const int w = tid >> 5;
    const int lane = tid & 31;

    const size_t rowbase = (size_t)b * SS + (size_t)n * STEP;
    const int kcnt = (n == NB - 1) ? 128 : 256;

    const __half* Qg = Q + rowbase * DD + h * HD;
    const __half* Kg = K + rowbase * DD + h * HD;
    const __half* Vg = V + rowbase * DD + h * HD;
    for (int idx = tid; idx < 128 * 8; idx += 256) {
        int r = idx >> 3, c = idx & 7;
        *(uint4*)(sm + ATTN_Q_OFF + r * AP + c * 16) =
            *(const uint4*)(Qg + (size_t)r * DD + c * 8);
    }
    for (int idx = tid; idx < kcnt * 8; idx += 256) {
        int r = idx >> 3, c = idx & 7;
        *(uint4*)(sm + ATTN_K_OFF + r * AP + c * 16) =
            *(const uint4*)(Kg + (size_t)r * DD + c * 8);
        *(uint4*)(sm + ATTN_V_OFF + r * AP + c * 16) =
            *(const uint4*)(Vg + (size_t)r * DD + c * 8);
    }
    __syncthreads();

    uint32_t qf[4][4];
    {
        const uint32_t a_row = (uint32_t)(w * 16 + (lane & 15));
        const uint32_t a_sel = (uint32_t)(lane >> 4);
        #pragma unroll
        for (int t = 0; t < 4; t++)
            ldsm_x4(qf[t], sb + ATTN_Q_OFF + a_row * AP + (2 * t + a_sel) * 16);
    }

    float oacc[8][4];
    #pragma unroll
    for (int j = 0; j < 8; j++)
        #pragma unroll
        for (int e = 0; e < 4; e++) oacc[j][e] = 0.f;
    float rs_lo = 0.f, rs_hi = 0.f;

    const uint32_t b_row = (uint32_t)((lane & 7) + ((lane >> 4) << 3));
    const uint32_t b_sel = (uint32_t)((lane >> 3) & 1);
    const uint32_t v_row = (uint32_t)((lane & 7) + (((lane >> 3) & 1) << 3));
    const uint32_t v_col = (uint32_t)(((lane >> 4) & 1) << 4);

    const int nch = kcnt >> 6;
    for (int ch = 0; ch < nch; ch++) {
        const int kb = ch * 64;

        float sacc[8][4];
        #pragma unroll
        for (int j = 0; j < 8; j++)
            #pragma unroll
            for (int e = 0; e < 4; e++) sacc[j][e] = 0.f;

        // t outer, g inner: 8 independent MMAs between accumulator reuses
        #pragma unroll
        for (int t = 0; t < 4; t++) {
            #pragma unroll
            for (int g = 0; g < 4; g++) {
                uint32_t kf[4];
                ldsm_x4(kf, sb + ATTN_K_OFF + (kb + g * 16 + b_row) * AP
                              + (2 * t + b_sel) * 16);
                mma16816h(sacc[2 * g],     qf[t], &kf[0]);
                mma16816h(sacc[2 * g + 1], qf[t], &kf[2]);
            }
        }

        uint32_t pa[4][4];
        #pragma unroll
        for (int j = 0; j < 8; j++) {
            float p0 = __expf(sacc[j][0] * 0.125f);
            float p1 = __expf(sacc[j][1] * 0.125f);
            float p2 = __expf(sacc[j][2] * 0.125f);
            float p3 = __expf(sacc[j][3] * 0.125f);
            rs_lo += p0 + p1;
            rs_hi += p2 + p3;
            pa[j >> 1][(j & 1) * 2 + 0] = h2u(p0, p1);
            pa[j >> 1][(j & 1) * 2 + 1] = h2u(p2, p3);
        }

        #pragma unroll
        for (int t = 0; t < 4; t++) {
            #pragma unroll
            for (int dp = 0; dp < 4; dp++) {
                uint32_t vf[4];
                ldsm_x4_t(vf, sb + ATTN_V_OFF + (kb + t * 16 + v_row) * AP
                                + dp * 32 + v_col);
                mma16816h(oacc[2 * dp],     pa[t], &vf[0]);
                mma16816h(oacc[2 * dp + 1], pa[t], &vf[2]);
            }
        }
    }

    rs_lo += __shfl_xor_sync(0xffffffffu, rs_lo, 1);
    rs_lo += __shfl_xor_sync(0xffffffffu, rs_lo, 2);
    rs_hi += __shfl_xor_sync(0xffffffffu, rs_hi, 1);
    rs_hi += __shfl_xor_sync(0xffffffffu, rs_hi, 2);
    const float il = 1.f / rs_lo;
    const float ih = 1.f / rs_hi;

    const size_t row = rowbase + w * 16 + (lane >> 2);
    const int col0 = h * HD + (lane & 3) * 2;
    #pragma unroll
    for (int j = 0; j < 8; j++) {
        int c = col0 + j * 8;
        *(__half2*)(AO + row * DD + c) =
            __floats2half2_rn(oacc[j][0] * il, oacc[j][1] * il);
        *(__half2*)(AO + (row + 8) * DD + c) =
            __floats2half2_rn(oacc[j][2] * ih, oacc[j][3] * ih);
    }
}

// ---------------------------------------------------------------------------
// Residual add + LayerNorm
// ---------------------------------------------------------------------------
__global__ void __launch_bounds__(256)
ln_kernel(const float* __restrict__ hid, const float* __restrict__ proj,
          const float* __restrict__ w, const float* __restrict__ bb,
          float* __restrict__ out)
{
    const int row = blockIdx.x;
    const int tid = threadIdx.x;

    float4 hv = *(const float4*)(hid  + (size_t)row * DD + tid * 4);
    float4 pv = *(const float4*)(proj + (size_t)row * DD + tid * 4);
    float x0 = hv.x + pv.x, x1 = hv.y + pv.y, x2 = hv.z + pv.z, x3 = hv.w + pv.w;

    __shared__ float red1[8];
    __shared__ float red2[8];

    float s = x0 + x1 + x2 + x3;
    #pragma unroll
    for (int off = 16; off > 0; off >>= 1) s += __shfl_xor_sync(0xffffffffu, s, off);
    if ((tid & 31) == 0) red1[tid >> 5] = s;
    __syncthreads();
    float tot = red1[0] + red1[1] + red1[2] + red1[3]
              + red1[4] + red1[5] + red1[6] + red1[7];
    float mean = tot * (1.f / DD);

    float d0 = x0 - mean, d1 = x1 - mean, d2 = x2 - mean, d3 = x3 - mean;
    float s2 = d0*d0 + d1*d1 + d2*d2 + d3*d3;
    #pragma unroll
    for (int off = 16; off > 0; off >>= 1) s2 += __shfl_xor_sync(0xffffffffu, s2, off);
    if ((tid & 31) == 0) red2[tid >> 5] = s2;
    __syncthreads();
    float tot2 = red2[0] + red2[1] + red2[2] + red2[3]
               + red2[4] + red2[5] + red2[6] + red2[7];
    float rstd = rsqrtf(tot2 * (1.f / DD) + 1e-5f);

    float4 wv = *(const float4*)(w  + tid * 4);
    float4 bv = *(const float4*)(bb + tid * 4);
    float4 ov;
    ov.x = d0 * rstd * wv.x + bv.x;
    ov.y = d1 * rstd * wv.y + bv.y;
    ov.z = d2 * rstd * wv.z + bv.z;
    ov.w = d3 * rstd * wv.w + bv.w;
    *(float4*)(out + (size_t)row * DD + tid * 4) = ov;
}

// ---------------------------------------------------------------------------
extern "C" void kernel_launch(void* const* d_in, const int* in_sizes, int n_in,
                              void* d_out, int out_size)
{
    const float* hid = (const float*)d_in[0];
    const float* Wq  = (const float*)d_in[1];
    const float* bq  = (const float*)d_in[2];
    const float* Wk  = (const float*)d_in[3];
    const float* bk  = (const float*)d_in[4];
    const float* Wv  = (const float*)d_in[5];
    const float* bv  = (const float*)d_in[6];
    const float* Wo  = (const float*)d_in[7];
    const float* bo  = (const float*)d_in[8];
    const float* lnw = (const float*)d_in[9];
    const float* lnb = (const float*)d_in[10];
    float* out = (float*)d_out;

    __half *Qh, *Kh, *Vh, *AOh;
    float *Pb;
    cudaGetSymbolAddress((void**)&Qh,  g_Qh);
    cudaGetSymbolAddress((void**)&Kh,  g_Kh);
    cudaGetSymbolAddress((void**)&Vh,  g_Vh);
    cudaGetSymbolAddress((void**)&AOh, g_AOh);
    cudaGetSymbolAddress((void**)&Pb,  g_P);

    __half *hidh, *wqt, *wkt, *wvt, *wot;
    cudaGetSymbolAddress((void**)&hidh, g_hidh);
    cudaGetSymbolAddress((void**)&wqt,  g_wqt);
    cudaGetSymbolAddress((void**)&wkt,  g_wkt);
    cudaGetSymbolAddress((void**)&wvt,  g_wvt);
    cudaGetSymbolAddress((void**)&wot,  g_wot);

    static bool attr_set = false;
    if (!attr_set) {
        cudaFuncSetAttribute(attn_tc,
                             cudaFuncAttributeMaxDynamicSharedMemorySize, ATTN_SMEM);
        cudaFuncSetAttribute(gemm_qkv,
                             cudaFuncAttributeMaxDynamicSharedMemorySize, GEMM_SMEM);
        cudaFuncSetAttribute(gemm_h,
                             cudaFuncAttributeMaxDynamicSharedMemorySize, GEMM_SMEM);
        attr_set = true;
    }

    // fp16 conversions: hidden states + all 4 weights (single fused launch)
    cvt_h<<<MM * DD / (256 * 8), 256>>>(hid, hidh);
    dim3 tg(32, 32, 4);
    cvt_h_T4<<<tg, 256>>>(Wq, Wk, Wv, Wo, wqt, wkt, wvt, wot);

    // Fused Q/K/V projections (fp16 HMMA, fp16 out)
    dim3 gq(DD / 128, MM / 128, 3);  // (8, 64, 3)
    gemm_qkv<<<gq, 256, GEMM_SMEM>>>(hidh, wqt, wkt, wvt, bq, bk, bv, Qh, Kh, Vh);

    // Tensor-core attention (fp16 in/out), 2 CTAs/SM
    dim3 ag(HH, NB, BB);             // (16, 32, 2)
    attn_tc<<<ag, 256, ATTN_SMEM>>>(Qh, Kh, Vh, AOh);

    // O projection (fp32 out)
    dim3 gg(DD / 128, MM / 128);     // (8, 64)
    gemm_h<<<gg, 256, GEMM_SMEM>>>(AOh, wot, bo, Pb);

    // Residual + LayerNorm
    ln_kernel<<<MM, 256>>>(hid, Pb, lnw, lnb, out);
}